// round 1
// baseline (speedup 1.0000x reference)
#include <cuda_runtime.h>
#include <math.h>

// Problem constants
#define BB   8
#define TT   10
#define HH   64
#define WW   64
#define HID  64
#define PRED 10
#define PIX  (HH*WW)            // 4096
#define NST  (BB*HID*PIX)       // 2,097,152 floats per state buffer

// ---------------------------------------------------------------------------
// Scratch (device globals; no runtime allocation allowed)
// ---------------------------------------------------------------------------
__device__ float g_eh0[2*NST];
__device__ float g_ec0[NST];
__device__ float g_eh1[2*NST];
__device__ float g_ec1[NST];
__device__ float g_dh0[2*NST];
__device__ float g_dc0[NST];
__device__ float g_dh1[2*NST];
__device__ float g_dc1[NST];

#define WT_BIG (HID*HID*9*4)    // 147456
__device__ float g_wt_e0x[HID*1*9*4];
__device__ float g_wt_e0h[WT_BIG];
__device__ float g_wt_e1x[WT_BIG];
__device__ float g_wt_e1h[WT_BIG];
__device__ float g_wt_d0x[WT_BIG];
__device__ float g_wt_d0h[WT_BIG];
__device__ float g_wt_d1x[WT_BIG];
__device__ float g_wt_d1h[WT_BIG];

// ---------------------------------------------------------------------------
// Weight transform: (4*HID, Cin, 3, 3) -> [co][cin][tap][gate] (gate innermost,
// 16B-aligned groups so the cell kernel can fetch 4 gate weights as one float4)
// ---------------------------------------------------------------------------
__global__ void transform_w_kernel(const float* __restrict__ w,
                                   float* __restrict__ wt, int cin)
{
    int i = blockIdx.x * blockDim.x + threadIdx.x;
    int n = HID * cin * 9 * 4;
    if (i >= n) return;
    int gate = i & 3;
    int rest = i >> 2;
    int tap  = rest % 9;
    int rc   = rest / 9;
    int cc   = rc % cin;
    int co   = rc / cin;
    wt[i] = w[((gate*HID + co)*cin + cc)*9 + tap];
}

__device__ __forceinline__ float sigf(float x) { return 1.f / (1.f + expf(-x)); }

// ---------------------------------------------------------------------------
// Fused ConvLSTM cell:
//   pre[g,co] = conv3x3(x, Wx)[g,co] + conv3x3(h, Wh)[g,co] + Wc[g,co]*c + b[g,co]
//   i,f,o = sigmoid; g = tanh; c' = f*c + i*g; h' = o*tanh(c')
// Block: 128 threads. Tile: 32 wide x 16 tall. Thread: 4 pixels x 2 co x 4 gates.
// gridDim = (8 tiles, B, HID/2)
// ---------------------------------------------------------------------------
template<int CIN>
__global__ void __launch_bounds__(128)
cell_kernel(const float* __restrict__ xin, int xbs,
            const float* __restrict__ wxt,
            const float* __restrict__ hin,
            const float* __restrict__ wht,
            const float* __restrict__ Wc,
            const float* __restrict__ bias,
            const float* __restrict__ cst,
            float* __restrict__ hout,
            float* __restrict__ cout)
{
    const int tid  = threadIdx.x;
    const int tx   = tid & 31;        // 0..31 (x within tile)
    const int tyq  = tid >> 5;        // 0..3  (row-quad)
    const int tile = blockIdx.x;      // 0..7
    const int x0   = (tile & 1) * 32;
    const int y0   = (tile >> 1) * 16;
    const int b    = blockIdx.y;
    const int co0  = blockIdx.z * 2;

    __shared__ float s_in[18][34];    // 16+2 halo rows, 32+2 halo cols

    float acc[2][4][4];
    #pragma unroll
    for (int a = 0; a < 2; a++)
        #pragma unroll
        for (int g = 0; g < 4; g++)
            #pragma unroll
            for (int r = 0; r < 4; r++) acc[a][g][r] = 0.f;

    #pragma unroll
    for (int s = 0; s < 2; s++) {
        const float* inb = s ? (hin + (size_t)b * (HID * PIX))
                             : (xin + (size_t)b * xbs);
        const int nc = s ? HID : CIN;
        const float4* wtb = (const float4*)(s ? wht : wxt);

        for (int c = 0; c < nc; c++) {
            __syncthreads();
            const float* plane = inb + c * PIX;
            for (int idx = tid; idx < 18 * 34; idx += 128) {
                int ry = idx / 34, rx = idx - ry * 34;
                int gy = y0 + ry - 1, gx = x0 + rx - 1;
                float v = 0.f;
                if ((unsigned)gy < (unsigned)HH && (unsigned)gx < (unsigned)WW)
                    v = plane[gy * WW + gx];
                s_in[ry][rx] = v;
            }
            __syncthreads();

            const float4* w0p = wtb + ((size_t)co0 * nc + c) * 9;
            const float4* w1p = w0p + (size_t)nc * 9;
            #pragma unroll
            for (int tap = 0; tap < 9; tap++) {
                const int dy = tap / 3, dx = tap - dy * 3;
                float4 w0 = __ldg(w0p + tap);
                float4 w1 = __ldg(w1p + tap);
                #pragma unroll
                for (int r = 0; r < 4; r++) {
                    float v = s_in[tyq * 4 + r + dy][tx + dx];
                    acc[0][0][r] += w0.x * v;
                    acc[0][1][r] += w0.y * v;
                    acc[0][2][r] += w0.z * v;
                    acc[0][3][r] += w0.w * v;
                    acc[1][0][r] += w1.x * v;
                    acc[1][1][r] += w1.y * v;
                    acc[1][2][r] += w1.z * v;
                    acc[1][3][r] += w1.w * v;
                }
            }
        }
    }

    // LSTM pointwise epilogue
    #pragma unroll
    for (int ci2 = 0; ci2 < 2; ci2++) {
        const int co = co0 + ci2;
        #pragma unroll
        for (int r = 0; r < 4; r++) {
            int y = y0 + tyq * 4 + r;
            int x = x0 + tx;
            int ppix = y * WW + x;
            int base = co * PIX + ppix;          // within (HID,H,W)
            int bb   = b * HID * PIX + base;     // within (B,HID,H,W)
            float cold = cst[bb];
            float p0 = acc[ci2][0][r] + Wc[0*HID*PIX + base] * cold + bias[0*HID*PIX + base];
            float p1 = acc[ci2][1][r] + Wc[1*HID*PIX + base] * cold + bias[1*HID*PIX + base];
            float p2 = acc[ci2][2][r] + Wc[2*HID*PIX + base] * cold + bias[2*HID*PIX + base];
            float p3 = acc[ci2][3][r] + Wc[3*HID*PIX + base] * cold + bias[3*HID*PIX + base];
            float ig = sigf(p0);
            float fg = sigf(p1);
            float gg = tanhf(p2);
            float og = sigf(p3);
            float cn = fg * cold + ig * gg;
            cout[bb] = cn;
            hout[bb] = og * tanhf(cn);
        }
    }
}

// ---------------------------------------------------------------------------
// Final 3x3 conv (HID->1) + bias + sigmoid, per decoded frame
// out layout: (B, PRED, 1, H, W)
// ---------------------------------------------------------------------------
__global__ void __launch_bounds__(256)
final_conv_kernel(const float* __restrict__ h1,
                  const float* __restrict__ fw,
                  const float* __restrict__ fb,
                  float* __restrict__ out, int t)
{
    __shared__ float s_w[HID * 9];
    int tid = threadIdx.x;
    for (int i = tid; i < HID * 9; i += 256) s_w[i] = fw[i];
    __syncthreads();

    int pix = blockIdx.x * 256 + tid;   // 0..4095
    int b   = blockIdx.y;
    int y = pix >> 6, x = pix & 63;
    const float* hb = h1 + (size_t)b * HID * PIX;
    float sum = fb[0];
    for (int c = 0; c < HID; c++) {
        const float* plane = hb + c * PIX;
        #pragma unroll
        for (int tap = 0; tap < 9; tap++) {
            int dy = tap / 3 - 1, dx = tap % 3 - 1;
            int gy = y + dy, gx = x + dx;
            if ((unsigned)gy < 64u && (unsigned)gx < 64u)
                sum += s_w[c * 9 + tap] * plane[gy * 64 + gx];
        }
    }
    out[(size_t)b * (PRED * PIX) + t * PIX + pix] = 1.f / (1.f + expf(-sum));
}

// ---------------------------------------------------------------------------
// Launch: fully static sequence of kernels; graph-capturable, alloc-free.
// ---------------------------------------------------------------------------
extern "C" void kernel_launch(void* const* d_in, const int* in_sizes, int n_in,
                              void* d_out, int out_size)
{
    const float* x    = (const float*)d_in[0];
    const float* e0Wx = (const float*)d_in[1];
    const float* e0Wh = (const float*)d_in[2];
    const float* e0Wc = (const float*)d_in[3];
    const float* e0b  = (const float*)d_in[4];
    const float* e1Wx = (const float*)d_in[5];
    const float* e1Wh = (const float*)d_in[6];
    const float* e1Wc = (const float*)d_in[7];
    const float* e1b  = (const float*)d_in[8];
    const float* d0Wx = (const float*)d_in[9];
    const float* d0Wh = (const float*)d_in[10];
    const float* d0Wc = (const float*)d_in[11];
    const float* d0b  = (const float*)d_in[12];
    const float* d1Wx = (const float*)d_in[13];
    const float* d1Wh = (const float*)d_in[14];
    const float* d1Wc = (const float*)d_in[15];
    const float* d1b  = (const float*)d_in[16];
    const float* finw = (const float*)d_in[17];
    const float* finb = (const float*)d_in[18];
    float* out = (float*)d_out;

    float *eh0, *ec0, *eh1, *ec1, *dh0, *dc0, *dh1, *dc1;
    cudaGetSymbolAddress((void**)&eh0, g_eh0);
    cudaGetSymbolAddress((void**)&ec0, g_ec0);
    cudaGetSymbolAddress((void**)&eh1, g_eh1);
    cudaGetSymbolAddress((void**)&ec1, g_ec1);
    cudaGetSymbolAddress((void**)&dh0, g_dh0);
    cudaGetSymbolAddress((void**)&dc0, g_dc0);
    cudaGetSymbolAddress((void**)&dh1, g_dh1);
    cudaGetSymbolAddress((void**)&dc1, g_dc1);

    float *wte0x, *wte0h, *wte1x, *wte1h, *wtd0x, *wtd0h, *wtd1x, *wtd1h;
    cudaGetSymbolAddress((void**)&wte0x, g_wt_e0x);
    cudaGetSymbolAddress((void**)&wte0h, g_wt_e0h);
    cudaGetSymbolAddress((void**)&wte1x, g_wt_e1x);
    cudaGetSymbolAddress((void**)&wte1h, g_wt_e1h);
    cudaGetSymbolAddress((void**)&wtd0x, g_wt_d0x);
    cudaGetSymbolAddress((void**)&wtd0h, g_wt_d0h);
    cudaGetSymbolAddress((void**)&wtd1x, g_wt_d1x);
    cudaGetSymbolAddress((void**)&wtd1h, g_wt_d1h);

    // Weight transforms (cheap, once per replay)
    const int nsmall = HID * 1 * 9 * 4;
    transform_w_kernel<<<(nsmall + 255) / 256, 256>>>(e0Wx, wte0x, 1);
    transform_w_kernel<<<(WT_BIG + 255) / 256, 256>>>(e0Wh, wte0h, HID);
    transform_w_kernel<<<(WT_BIG + 255) / 256, 256>>>(e1Wx, wte1x, HID);
    transform_w_kernel<<<(WT_BIG + 255) / 256, 256>>>(e1Wh, wte1h, HID);
    transform_w_kernel<<<(WT_BIG + 255) / 256, 256>>>(d0Wx, wtd0x, HID);
    transform_w_kernel<<<(WT_BIG + 255) / 256, 256>>>(d0Wh, wtd0h, HID);
    transform_w_kernel<<<(WT_BIG + 255) / 256, 256>>>(d1Wx, wtd1x, HID);
    transform_w_kernel<<<(WT_BIG + 255) / 256, 256>>>(d1Wh, wtd1h, HID);

    // Zero initial states (only buffers read at t=0)
    size_t sb = (size_t)NST * sizeof(float);
    cudaMemsetAsync(eh0, 0, sb);
    cudaMemsetAsync(ec0, 0, sb);
    cudaMemsetAsync(eh1, 0, sb);
    cudaMemsetAsync(ec1, 0, sb);
    cudaMemsetAsync(dh0, 0, sb);
    cudaMemsetAsync(dc0, 0, sb);
    cudaMemsetAsync(dh1, 0, sb);
    cudaMemsetAsync(dc1, 0, sb);

    dim3 grid(8, BB, HID / 2), blk(128);

    // Encoder: 10 steps, 2 layers
    for (int t = 0; t < TT; t++) {
        int r = t & 1, w = r ^ 1;
        cell_kernel<1><<<grid, blk>>>(x + t * PIX, TT * PIX, wte0x,
                                      eh0 + r * NST, wte0h,
                                      e0Wc, e0b, ec0,
                                      eh0 + w * NST, ec0);
        cell_kernel<HID><<<grid, blk>>>(eh0 + w * NST, HID * PIX, wte1x,
                                        eh1 + r * NST, wte1h,
                                        e1Wc, e1b, ec1,
                                        eh1 + w * NST, ec1);
    }
    // After t=9 (r=1,w=0): final encoder h1 lives in eh1[0]

    // Decoder: 10 steps, 2 layers + final conv per step
    for (int t = 0; t < PRED; t++) {
        int r = t & 1, w = r ^ 1;
        const float* s = (t == 0) ? eh1 : (dh1 + r * NST);
        cell_kernel<HID><<<grid, blk>>>(s, HID * PIX, wtd0x,
                                        dh0 + r * NST, wtd0h,
                                        d0Wc, d0b, dc0,
                                        dh0 + w * NST, dc0);
        cell_kernel<HID><<<grid, blk>>>(dh0 + w * NST, HID * PIX, wtd1x,
                                        dh1 + r * NST, wtd1h,
                                        d1Wc, d1b, dc1,
                                        dh1 + w * NST, dc1);
        final_conv_kernel<<<dim3(16, BB), 256>>>(dh1 + w * NST, finw, finb, out, t);
    }
}